// round 2
// baseline (speedup 1.0000x reference)
#include <cuda_runtime.h>
#include <cuda_bf16.h>

// Per-row (8 fp32):
//   midv = ascending-sorted row[3] (descending rank 4)
//   out  = softmax(row) * (row > midv)
// 2 rows per thread, 4 front-batched streaming LDG.128, streaming STG.128.

#define CSWAP(a, b)                         \
    do {                                    \
        float _lo = fminf((a), (b));        \
        float _hi = fmaxf((a), (b));        \
        (a) = _lo;                          \
        (b) = _hi;                          \
    } while (0)

__device__ __forceinline__ void row_op(float4 a, float4 b, float4& o0, float4& o1)
{
    float v0 = a.x, v1 = a.y, v2 = a.z, v3 = a.w;
    float v4 = b.x, v5 = b.y, v6 = b.z, v7 = b.w;

    // 19-comparator sorting network; need ascending index 3 and the max.
    float s0 = v0, s1 = v1, s2 = v2, s3 = v3, s4 = v4, s5 = v5, s6 = v6, s7 = v7;
    CSWAP(s0, s1); CSWAP(s2, s3); CSWAP(s4, s5); CSWAP(s6, s7);
    CSWAP(s0, s2); CSWAP(s1, s3); CSWAP(s4, s6); CSWAP(s5, s7);
    CSWAP(s1, s2); CSWAP(s5, s6); CSWAP(s0, s4); CSWAP(s3, s7);
    CSWAP(s1, s5); CSWAP(s2, s6);
    CSWAP(s1, s4); CSWAP(s3, s6);
    CSWAP(s2, s4); CSWAP(s3, s5);
    CSWAP(s3, s4);
    const float midv = s3;
    const float rmax = s7;

    float e0 = __expf(v0 - rmax);
    float e1 = __expf(v1 - rmax);
    float e2 = __expf(v2 - rmax);
    float e3 = __expf(v3 - rmax);
    float e4 = __expf(v4 - rmax);
    float e5 = __expf(v5 - rmax);
    float e6 = __expf(v6 - rmax);
    float e7 = __expf(v7 - rmax);

    float sum = ((e0 + e1) + (e2 + e3)) + ((e4 + e5) + (e6 + e7));
    float inv = 1.0f / sum;

    o0.x = (v0 > midv) ? e0 * inv : 0.0f;
    o0.y = (v1 > midv) ? e1 * inv : 0.0f;
    o0.z = (v2 > midv) ? e2 * inv : 0.0f;
    o0.w = (v3 > midv) ? e3 * inv : 0.0f;
    o1.x = (v4 > midv) ? e4 * inv : 0.0f;
    o1.y = (v5 > midv) ? e5 * inv : 0.0f;
    o1.z = (v6 > midv) ? e6 * inv : 0.0f;
    o1.w = (v7 > midv) ? e7 * inv : 0.0f;
}

__global__ void __launch_bounds__(256) hnet3_masked_softmax_kernel(
    const float4* __restrict__ in, float4* __restrict__ out, int nrows)
{
    // Each thread handles 2 consecutive rows = 4 float4s.
    int t = blockIdx.x * blockDim.x + threadIdx.x;
    int r0 = 2 * t;
    if (r0 >= nrows) return;

    const bool two = (r0 + 1) < nrows;

    // Front-batch all independent streaming loads (MLP=4 per thread).
    float4 a0 = __ldcs(&in[4 * t + 0]);
    float4 b0 = __ldcs(&in[4 * t + 1]);
    float4 a1, b1;
    if (two) {
        a1 = __ldcs(&in[4 * t + 2]);
        b1 = __ldcs(&in[4 * t + 3]);
    }

    float4 o0, o1;
    row_op(a0, b0, o0, o1);
    __stcs(&out[4 * t + 0], o0);
    __stcs(&out[4 * t + 1], o1);

    if (two) {
        float4 o2, o3;
        row_op(a1, b1, o2, o3);
        __stcs(&out[4 * t + 2], o2);
        __stcs(&out[4 * t + 3], o3);
    }
}

extern "C" void kernel_launch(void* const* d_in, const int* in_sizes, int n_in,
                              void* d_out, int out_size)
{
    const float4* in = (const float4*)d_in[0];
    float4* out = (float4*)d_out;
    const int nrows = in_sizes[0] / 8;   // 8 fp32 per group

    const int threads = 256;
    const int rows_per_block = threads * 2;
    const int blocks = (nrows + rows_per_block - 1) / rows_per_block;
    hnet3_masked_softmax_kernel<<<blocks, threads>>>(in, out, nrows);
}

// round 3
// speedup vs baseline: 1.0242x; 1.0242x over previous
#include <cuda_runtime.h>
#include <cuda_bf16.h>

// Per-row (8 fp32):
//   midv = ascending-sorted row[3]  (== value at descending rank 4)
//   out  = softmax(row) * (row > midv)
// One thread per row (R1 shape, occ-proven) + streaming ld/st hints.

#define CSWAP(a, b)                         \
    do {                                    \
        float _lo = fminf((a), (b));        \
        float _hi = fmaxf((a), (b));        \
        (a) = _lo;                          \
        (b) = _hi;                          \
    } while (0)

__global__ void __launch_bounds__(256) hnet3_masked_softmax_kernel(
    const float4* __restrict__ in, float4* __restrict__ out, int nrows)
{
    int r = blockIdx.x * blockDim.x + threadIdx.x;
    if (r >= nrows) return;

    const float4 a = __ldcs(&in[2 * r + 0]);
    const float4 b = __ldcs(&in[2 * r + 1]);

    float v0 = a.x, v1 = a.y, v2 = a.z, v3 = a.w;
    float v4 = b.x, v5 = b.y, v6 = b.z, v7 = b.w;

    // 19-comparator sorting network; ascending index 3 = midv, index 7 = max.
    float s0 = v0, s1 = v1, s2 = v2, s3 = v3, s4 = v4, s5 = v5, s6 = v6, s7 = v7;
    CSWAP(s0, s1); CSWAP(s2, s3); CSWAP(s4, s5); CSWAP(s6, s7);
    CSWAP(s0, s2); CSWAP(s1, s3); CSWAP(s4, s6); CSWAP(s5, s7);
    CSWAP(s1, s2); CSWAP(s5, s6); CSWAP(s0, s4); CSWAP(s3, s7);
    CSWAP(s1, s5); CSWAP(s2, s6);
    CSWAP(s1, s4); CSWAP(s3, s6);
    CSWAP(s2, s4); CSWAP(s3, s5);
    CSWAP(s3, s4);
    const float midv = s3;
    const float rmax = s7;

    float e0 = __expf(v0 - rmax);
    float e1 = __expf(v1 - rmax);
    float e2 = __expf(v2 - rmax);
    float e3 = __expf(v3 - rmax);
    float e4 = __expf(v4 - rmax);
    float e5 = __expf(v5 - rmax);
    float e6 = __expf(v6 - rmax);
    float e7 = __expf(v7 - rmax);

    float sum = ((e0 + e1) + (e2 + e3)) + ((e4 + e5) + (e6 + e7));
    float inv = 1.0f / sum;

    float4 o0, o1;
    o0.x = (v0 > midv) ? e0 * inv : 0.0f;
    o0.y = (v1 > midv) ? e1 * inv : 0.0f;
    o0.z = (v2 > midv) ? e2 * inv : 0.0f;
    o0.w = (v3 > midv) ? e3 * inv : 0.0f;
    o1.x = (v4 > midv) ? e4 * inv : 0.0f;
    o1.y = (v5 > midv) ? e5 * inv : 0.0f;
    o1.z = (v6 > midv) ? e6 * inv : 0.0f;
    o1.w = (v7 > midv) ? e7 * inv : 0.0f;

    __stcs(&out[2 * r + 0], o0);
    __stcs(&out[2 * r + 1], o1);
}

extern "C" void kernel_launch(void* const* d_in, const int* in_sizes, int n_in,
                              void* d_out, int out_size)
{
    const float4* in = (const float4*)d_in[0];
    float4* out = (float4*)d_out;
    const int nrows = in_sizes[0] / 8;   // 8 fp32 per group

    const int threads = 256;
    const int blocks = (nrows + threads - 1) / threads;
    hnet3_masked_softmax_kernel<<<blocks, threads>>>(in, out, nrows);
}